// round 5
// baseline (speedup 1.0000x reference)
#include <cuda_runtime.h>

#define Bb 4
#define Ss 1024
#define Dd 32
#define Hh 32
#define NBLK 128           // 4 batches x 32 row-slices; all wave-1
#define NTHR 512           // 16 warps
#define WPAD 33            // padded row stride (floats) for per-lane reads

// partial sums: [b][h][slice]
__device__ float g_ps [Bb * Hh * 32];
__device__ float g_psv[Bb * Hh * 32];
__device__ unsigned g_cnt;   // monotonic epoch counter (+128 per call)

__global__ void __launch_bounds__(NTHR, 1) foaa_fused(
    const float* __restrict__ x,
    const float* __restrict__ Wk, const float* __restrict__ bk,
    const float* __restrict__ Wv, const float* __restrict__ bv,
    const float* __restrict__ Wo, const float* __restrict__ bo,
    float* __restrict__ out)
{
    const int b     = blockIdx.x >> 5;
    const int slice = blockIdx.x & 31;
    const int tid   = threadIdx.x;
    const int w     = tid >> 5;
    const int lane  = tid & 31;

    __shared__ __align__(16) float4 xs4[Dd * Dd / 4];  // 32 rows x 8 f4, linear
    __shared__ float wk_s[Hh * WPAD];
    __shared__ float wv_s[Hh * WPAD];
    __shared__ float wo_s[Dd * WPAD];
    __shared__ float pss [Hh * WPAD];
    __shared__ float psv [Hh * WPAD];
    __shared__ float sred[16 * WPAD], svred[16 * WPAD];
    __shared__ float c_s[Hh];
    __shared__ __align__(16) float y[Dd];
    __shared__ float s_bo[Dd];

    // ---- Preamble: coalesced global -> smem (1024 float4 tasks) ----
    #pragma unroll
    for (int t2 = 0; t2 < 2; t2++) {
        int task = tid + t2 * NTHR;
        int arr = task >> 8, idx = task & 255;
        if (arr == 0) {
            xs4[idx] = ((const float4*)(x + ((size_t)b * Ss + slice * 32) * Dd))[idx];
        } else {
            const float* src = (arr == 1) ? Wk : ((arr == 2) ? Wv : Wo);
            float*       dst = (arr == 1) ? wk_s : ((arr == 2) ? wv_s : wo_s);
            float4 v = ((const float4*)src)[idx];
            int e = idx * 4, r = e >> 5, c0 = e & 31;
            dst[r * WPAD + c0 + 0] = v.x;
            dst[r * WPAD + c0 + 1] = v.y;
            dst[r * WPAD + c0 + 2] = v.z;
            dst[r * WPAD + c0 + 3] = v.w;
        }
    }
    if (tid < 8) ((float4*)s_bo)[tid] = ((const float4*)bo)[tid];
    __syncthreads();

    // ---- Per-lane head weights into registers (conflict-free LDS) ----
    float wkr[32], wvr[32];
    #pragma unroll
    for (int c = 0; c < 32; c++) {
        wkr[c] = wk_s[lane * WPAD + c];
        wvr[c] = wv_s[lane * WPAD + c];
    }

    // ---- Stage 1: warp w handles rows 2w, 2w+1; lane = head ----
    float s = 0.0f, sv = 0.0f;
    #pragma unroll
    for (int rr = 0; rr < 2; rr++) {
        const float4* xr = xs4 + (w * 2 + rr) * 8;
        float kp0 = 0.f, kp1 = 0.f, vp0 = 0.f, vp1 = 0.f;
        #pragma unroll
        for (int q = 0; q < 8; q += 2) {
            float4 a = xr[q];       // uniform broadcast
            float4 bq = xr[q + 1];
            kp0 = fmaf(a.x,  wkr[4*q+0], kp0); kp0 = fmaf(a.y,  wkr[4*q+1], kp0);
            kp0 = fmaf(a.z,  wkr[4*q+2], kp0); kp0 = fmaf(a.w,  wkr[4*q+3], kp0);
            vp0 = fmaf(a.x,  wvr[4*q+0], vp0); vp0 = fmaf(a.y,  wvr[4*q+1], vp0);
            vp0 = fmaf(a.z,  wvr[4*q+2], vp0); vp0 = fmaf(a.w,  wvr[4*q+3], vp0);
            kp1 = fmaf(bq.x, wkr[4*q+4], kp1); kp1 = fmaf(bq.y, wkr[4*q+5], kp1);
            kp1 = fmaf(bq.z, wkr[4*q+6], kp1); kp1 = fmaf(bq.w, wkr[4*q+7], kp1);
            vp1 = fmaf(bq.x, wvr[4*q+4], vp1); vp1 = fmaf(bq.y, wvr[4*q+5], vp1);
            vp1 = fmaf(bq.z, wvr[4*q+6], vp1); vp1 = fmaf(bq.w, wvr[4*q+7], vp1);
        }
        float e = __expf(kp0 + kp1);       // bk cancels in softmax
        s += e;
        sv = fmaf(e, vp0 + vp1, sv);       // bv added at stage 2
    }
    sred [w * WPAD + lane] = s;
    svred[w * WPAD + lane] = sv;
    __syncthreads();

    // ---- Block-reduce 16 warps (fixed order), publish slice partials ----
    if (w == 0) {
        float S = 0.f, SV = 0.f;
        #pragma unroll
        for (int k2 = 0; k2 < 16; k2++) {
            S  += sred [k2 * WPAD + lane];
            SV += svred[k2 * WPAD + lane];
        }
        g_ps [(b * Hh + lane) * 32 + slice] = S;
        g_psv[(b * Hh + lane) * 32 + slice] = SV;
        __threadfence();
    }
    __syncthreads();

    // ---- Grid barrier (epoch-based, graph-safe) ----
    if (tid == 0) {
        unsigned c0 = atomicAdd(&g_cnt, 1u);
        unsigned target = ((c0 >> 7) + 1u) << 7;   // next multiple of 128
        unsigned vcur;
        do {
            asm volatile("ld.acquire.gpu.u32 %0, [%1];"
                         : "=r"(vcur) : "l"(&g_cnt));
        } while (vcur < target);
    }
    __syncthreads();

    // ---- Stage 2: gather partials for batch b, finish softmax, matvec ----
    {
        int arr = tid >> 8, idx = tid & 255;       // 512 f4 tasks, 1/thread
        const float* src = arr ? (g_psv + b * 1024) : (g_ps + b * 1024);
        float*       dst = arr ? psv : pss;
        float4 v = ((const float4*)src)[idx];
        int e = idx * 4, h2 = e >> 5, c2 = e & 31;
        dst[h2 * WPAD + c2 + 0] = v.x;
        dst[h2 * WPAD + c2 + 1] = v.y;
        dst[h2 * WPAD + c2 + 2] = v.z;
        dst[h2 * WPAD + c2 + 3] = v.w;
    }
    __syncthreads();

    if (tid < Hh) {
        float S = 0.f, SV = 0.f;
        #pragma unroll
        for (int i = 0; i < 32; i++) {
            S  += pss[tid * WPAD + i];
            SV += psv[tid * WPAD + i];
        }
        c_s[tid] = SV / S + bv[tid];
    }
    __syncthreads();

    if (tid < Dd) {
        float acc = s_bo[tid];
        #pragma unroll
        for (int h2 = 0; h2 < Hh; h2++)
            acc = fmaf(c_s[h2], wo_s[tid * WPAD + h2], acc);
        y[tid] = acc;
    }
    __syncthreads();

    // ---- Broadcast 32 output rows (4 KB) for this slice ----
    if (tid < 256) {
        ((float4*)(out + ((size_t)b * Ss + slice * 32) * Dd))[tid] =
            ((const float4*)y)[tid & 7];
    }
}

extern "C" void kernel_launch(void* const* d_in, const int* in_sizes, int n_in,
                              void* d_out, int out_size)
{
    // metadata order: x, Wq, bq, Wk, bk, Wv, bv, Wo, bo
    const float* x  = (const float*)d_in[0];
    const float* Wk = (const float*)d_in[3];
    const float* bk = (const float*)d_in[4];
    const float* Wv = (const float*)d_in[5];
    const float* bv = (const float*)d_in[6];
    const float* Wo = (const float*)d_in[7];
    const float* bo = (const float*)d_in[8];
    float* out = (float*)d_out;

    foaa_fused<<<NBLK, NTHR>>>(x, Wk, bk, Wv, bv, Wo, bo, out);
}